// round 3
// baseline (speedup 1.0000x reference)
#include <cuda_runtime.h>

// Rotation_11364483465564 — diagonal phase rotation.
//
// a^T a = diag(0..D-1)  =>  M = expm(i*pi*angle*a^T a) is diagonal,
// M[n] = exp(i*theta*n), theta = fl32(pi_f32 * angle).  kron(M, I2) applies
// phase n to rows 2n and 2n+1 of the (2D, B) complex state.
//
// R2 change: full-occupancy streaming + per-block smem phase table.
//   - Each 256-thread block covers 256 consecutive vec4 of the plane =
//     4 rows = exactly 2 Fock indices n (= 2*bid, 2*bid+1).
//   - Threads 0..1 compute the two (c,s) pairs with accurate sincosf
//     (bit-identical argument rounding to the reference); everyone else
//     just streams: 2x LDG.128 + 8 FMA + 2x STG.128 + 1 LDS.64.
//   This is the "many warps AND light per-thread math" quadrant that
//   R0 (many warps, heavy math) and R1 (few warps, light math) left untested.
//
// Precision: arg = fl32(fl32(pi_f32*angle) * n), matching the reference's
// expm input rounding. Accurate sincosf (NOT __sincosf — too lossy at ~2e4).

#ifndef ROT_D
#define ROT_D 2048
#endif
#ifndef ROT_B
#define ROT_B 256
#endif

static constexpr int PLANE_FLOATS = 2 * ROT_D * ROT_B;   // 1,048,576
static constexpr int PLANE_VEC4   = PLANE_FLOATS / 4;    // 262,144
// 256 vec4 per block -> 1024 blocks; 64 vec4 per row, 2 rows per n,
// so one block = 2 n-values.

__global__ __launch_bounds__(256)
void rotation_phase_kernel(const float* __restrict__ angle,
                           const float* __restrict__ xr,
                           const float* __restrict__ xi,
                           float* __restrict__ out)
{
    __shared__ float2 cs[2];   // (cos, sin) for local n = 0, 1

    const int tid = threadIdx.x;

    if (tid < 2) {
        // theta = fl32(pi_f32 * angle) — identical rounding to reference.
        const float theta = 3.14159265358979323846f * __ldg(angle);
        const int n = 2 * blockIdx.x + tid;
        float s, c;
        sincosf(theta * (float)n, &s, &c);   // fl32(theta*n) matches ref arg
        cs[tid] = make_float2(c, s);
    }
    __syncthreads();

    const int gid = blockIdx.x * 256 + tid;      // vec4 index in plane
    // local n within block: vec4 128..255 belong to the second n
    const float2 p = cs[tid >> 7];
    const float c = p.x, s = p.y;

    const float4 r4 = reinterpret_cast<const float4*>(xr)[gid];
    const float4 i4 = reinterpret_cast<const float4*>(xi)[gid];

    float4 o_re, o_im;
    o_re.x = fmaf(c, r4.x, -s * i4.x);
    o_re.y = fmaf(c, r4.y, -s * i4.y);
    o_re.z = fmaf(c, r4.z, -s * i4.z);
    o_re.w = fmaf(c, r4.w, -s * i4.w);
    o_im.x = fmaf(s, r4.x,  c * i4.x);
    o_im.y = fmaf(s, r4.y,  c * i4.y);
    o_im.z = fmaf(s, r4.z,  c * i4.z);
    o_im.w = fmaf(s, r4.w,  c * i4.w);

    reinterpret_cast<float4*>(out)[gid]              = o_re;
    reinterpret_cast<float4*>(out)[gid + PLANE_VEC4] = o_im;
}

extern "C" void kernel_launch(void* const* d_in, const int* in_sizes, int n_in,
                              void* d_out, int out_size)
{
    (void)in_sizes; (void)n_in; (void)out_size;
    const float* angle = (const float*)d_in[0];
    // d_in[1] ('a' matrix) unused: a^T a = diag(0..D-1) analytically.
    const float* xr = (const float*)d_in[2];
    const float* xi = (const float*)d_in[3];
    float* out = (float*)d_out;

    rotation_phase_kernel<<<PLANE_VEC4 / 256, 256>>>(angle, xr, xi, out);
}